// round 1
// baseline (speedup 1.0000x reference)
#include <cuda_runtime.h>
#include <cstdint>

#define N_NODES 100000
#define N_EDGES 20000
#define NNZ     1000000
#define D       64

// Scratch (device globals: allocation-free per harness rules)
__device__ float g_Y1[N_NODES * D];          // X @ W1^T + b1
__device__ float g_S [N_NODES * D];          // segment_sum(Xe[edges], vertex)
__device__ int   g_deg[N_NODES];             // per-node incidence count
__device__ float g_W1T [D * D];              // W1_w transposed: [k][j]
__device__ float g_Wcat[192 * D];            // stacked folded weights [k][j]
__device__ float g_cvec[D];                  // b2 @ W^T

// ---------------------------------------------------------------------------
// K_pre: fold weights.
//   Wcat[k][j] (k<128)   = sum_m W2_w[m][k] * W_w[j][m]
//   Wcat[k][j] (k>=128)  = W_w[j][k-128]
//   W1T[k][j]            = W1_w[j][k]
//   cvec[j]              = sum_m W2_b[m] * W_w[j][m]
// ---------------------------------------------------------------------------
__global__ void k_pre(const float* __restrict__ W1_w,
                      const float* __restrict__ W2_w,
                      const float* __restrict__ W2_b,
                      const float* __restrict__ W_w) {
    __shared__ float WT[64 * 64];   // WT[m][j] = W_w[j][m]
    int tid = threadIdx.x;
    for (int i = tid; i < 4096; i += 256) {
        int j = i >> 6, m = i & 63;
        WT[m * 64 + j] = W_w[i];
    }
    __syncthreads();
    int idx = blockIdx.x * 256 + tid;
    if (idx < 192 * 64) {
        int k = idx >> 6, j = idx & 63;
        float v;
        if (k < 128) {
            float acc = 0.f;
            #pragma unroll 8
            for (int m = 0; m < 64; m++) acc += W2_w[m * 128 + k] * WT[m * 64 + j];
            v = acc;
        } else {
            v = W_w[j * 64 + (k - 128)];
        }
        g_Wcat[k * 64 + j] = v;
    } else if (idx < 192 * 64 + 4096) {
        int t = idx - 192 * 64;
        int k = t >> 6, j = t & 63;
        g_W1T[k * 64 + j] = W1_w[j * 64 + k];
    } else if (idx < 192 * 64 + 4096 + 64) {
        int j = idx - (192 * 64 + 4096);
        float acc = 0.f;
        for (int m = 0; m < 64; m++) acc += W2_b[m] * WT[m * 64 + j];
        g_cvec[j] = acc;
    }
}

// 16-FMA micro-kernel step
#define FMA16(a, b, acc)                                                     \
    acc[0][0] += a.x * b.x; acc[0][1] += a.x * b.y;                          \
    acc[0][2] += a.x * b.z; acc[0][3] += a.x * b.w;                          \
    acc[1][0] += a.y * b.x; acc[1][1] += a.y * b.y;                          \
    acc[1][2] += a.y * b.z; acc[1][3] += a.y * b.w;                          \
    acc[2][0] += a.z * b.x; acc[2][1] += a.z * b.y;                          \
    acc[2][2] += a.z * b.z; acc[2][3] += a.z * b.w;                          \
    acc[3][0] += a.w * b.x; acc[3][1] += a.w * b.y;                          \
    acc[3][2] += a.w * b.z; acc[3][3] += a.w * b.w;

// ---------------------------------------------------------------------------
// K1: Y1 = X @ W1^T + b1.   64-row tiles, 256 threads, 4x4 micro-tiles.
// ---------------------------------------------------------------------------
__global__ __launch_bounds__(256) void k_gemm_y1(const float* __restrict__ X,
                                                 const float* __restrict__ b1) {
    __shared__ float Xs[64][68];   // transposed: Xs[k][r]
    __shared__ float Ws[64][64];   // Ws[k][j]
    __shared__ float bs[64];
    int tid = threadIdx.x;
    int row0 = blockIdx.x * 64;

    for (int i = tid; i < 1024; i += 256)
        ((float4*)Ws)[i] = ((const float4*)g_W1T)[i];
    if (tid < 64) bs[tid] = b1[tid];
    #pragma unroll
    for (int i = 0; i < 4; i++) {
        int f = tid + i * 256;
        int r = f >> 4, k4 = f & 15;
        int row = row0 + r;
        float4 x = (row < N_NODES) ? ((const float4*)X)[row * 16 + k4]
                                   : make_float4(0.f, 0.f, 0.f, 0.f);
        Xs[k4 * 4 + 0][r] = x.x; Xs[k4 * 4 + 1][r] = x.y;
        Xs[k4 * 4 + 2][r] = x.z; Xs[k4 * 4 + 3][r] = x.w;
    }
    __syncthreads();

    int ty = tid >> 4, tx = tid & 15;
    int ty4 = ty * 4, tx4 = tx * 4;
    float acc[4][4] = {};
    #pragma unroll 16
    for (int k = 0; k < 64; k++) {
        float4 a = *(const float4*)&Xs[k][ty4];
        float4 b = *(const float4*)&Ws[k][tx4];
        FMA16(a, b, acc)
    }
    #pragma unroll
    for (int r = 0; r < 4; r++) {
        int row = row0 + ty4 + r;
        if (row < N_NODES) {
            float4 o;
            o.x = acc[r][0] + bs[tx4 + 0];
            o.y = acc[r][1] + bs[tx4 + 1];
            o.z = acc[r][2] + bs[tx4 + 2];
            o.w = acc[r][3] + bs[tx4 + 3];
            ((float4*)g_Y1)[row * 16 + tx] = o;
        }
    }
}

// ---------------------------------------------------------------------------
// K2: Xe[e] += Y1[v] for each incidence; also deg[v]++.  8 threads / incidence.
// ---------------------------------------------------------------------------
__device__ __forceinline__ void red_add_v4(float* p, float4 v) {
    asm volatile("red.global.add.v4.f32 [%0], {%1,%2,%3,%4};"
                 :: "l"(p), "f"(v.x), "f"(v.y), "f"(v.z), "f"(v.w) : "memory");
}

__global__ __launch_bounds__(256) void k_scatter_e(const int* __restrict__ vertex,
                                                   const int* __restrict__ edges,
                                                   float* __restrict__ XeOut) {
    int g = blockIdx.x * 256 + threadIdx.x;
    int i = g >> 3;
    if (i >= NNZ) return;
    int l = g & 7;
    int v = vertex[i];
    int e = edges[i];
    const float4* src = (const float4*)(g_Y1 + (size_t)v * 64) + l * 2;
    float*        dst = XeOut + (size_t)e * 64 + l * 8;
    float4 a = src[0], b = src[1];
    red_add_v4(dst, a);
    red_add_v4(dst + 4, b);
    if (l == 0) atomicAdd(&g_deg[v], 1);
}

// ---------------------------------------------------------------------------
// K3: S[v] += Xe[e] for each incidence.
// ---------------------------------------------------------------------------
__global__ __launch_bounds__(256) void k_scatter_v(const int* __restrict__ vertex,
                                                   const int* __restrict__ edges,
                                                   const float* __restrict__ Xe) {
    int g = blockIdx.x * 256 + threadIdx.x;
    int i = g >> 3;
    if (i >= NNZ) return;
    int l = g & 7;
    int v = vertex[i];
    int e = edges[i];
    const float4* src = (const float4*)(Xe + (size_t)e * 64) + l * 2;
    float*        dst = g_S + (size_t)v * 64 + l * 8;
    float4 a = src[0], b = src[1];
    red_add_v4(dst, a);
    red_add_v4(dst + 4, b);
}

// ---------------------------------------------------------------------------
// K4: out[v] = [0.5*deg*X[v] | 0.5*S[v] | 0.5*X0[v]] @ Wcat + 0.5*deg*cvec + Wb
//     K=192 processed as 3 chunks of 64 (one per source).
// ---------------------------------------------------------------------------
__global__ __launch_bounds__(256) void k_node_out(const float* __restrict__ X,
                                                  const float* __restrict__ X0,
                                                  const float* __restrict__ Wb,
                                                  float* __restrict__ out) {
    __shared__ float Xs[64][68];    // transposed chunk: Xs[k][r]
    __shared__ float Ws[64][64];    // Wcat chunk: Ws[k][j]
    __shared__ float degs[64];      // 0.5 * deg
    __shared__ float cv[64];        // cvec
    __shared__ float bb[64];        // W_b

    int tid = threadIdx.x;
    int row0 = blockIdx.x * 64;
    if (tid < 64) {
        int row = row0 + tid;
        degs[tid] = (row < N_NODES) ? 0.5f * (float)g_deg[row] : 0.f;
    } else if (tid < 128) {
        cv[tid - 64] = g_cvec[tid - 64];
    } else if (tid < 192) {
        bb[tid - 128] = Wb[tid - 128];
    }
    __syncthreads();

    int ty = tid >> 4, tx = tid & 15;
    int ty4 = ty * 4, tx4 = tx * 4;
    float acc[4][4] = {};

    #pragma unroll
    for (int kb = 0; kb < 3; kb++) {
        const float* src = (kb == 0) ? X : (kb == 1) ? g_S : X0;
        // load input chunk (transposed, scaled)
        #pragma unroll
        for (int i = 0; i < 4; i++) {
            int f = tid + i * 256;
            int r = f >> 4, k4 = f & 15;
            int row = row0 + r;
            float s = (kb == 0) ? degs[r] : 0.5f;
            float4 x = (row < N_NODES) ? ((const float4*)src)[row * 16 + k4]
                                       : make_float4(0.f, 0.f, 0.f, 0.f);
            Xs[k4 * 4 + 0][r] = s * x.x; Xs[k4 * 4 + 1][r] = s * x.y;
            Xs[k4 * 4 + 2][r] = s * x.z; Xs[k4 * 4 + 3][r] = s * x.w;
        }
        // load weight chunk
        const float4* wsrc = (const float4*)(g_Wcat + kb * 64 * 64);
        #pragma unroll
        for (int i = 0; i < 4; i++)
            ((float4*)Ws)[tid + i * 256] = wsrc[tid + i * 256];
        __syncthreads();

        #pragma unroll 16
        for (int k = 0; k < 64; k++) {
            float4 a = *(const float4*)&Xs[k][ty4];
            float4 b = *(const float4*)&Ws[k][tx4];
            FMA16(a, b, acc)
        }
        __syncthreads();
    }

    #pragma unroll
    for (int r = 0; r < 4; r++) {
        int row = row0 + ty4 + r;
        if (row < N_NODES) {
            float hd = degs[ty4 + r];
            float4 o;
            o.x = acc[r][0] + hd * cv[tx4 + 0] + bb[tx4 + 0];
            o.y = acc[r][1] + hd * cv[tx4 + 1] + bb[tx4 + 1];
            o.z = acc[r][2] + hd * cv[tx4 + 2] + bb[tx4 + 2];
            o.w = acc[r][3] + hd * cv[tx4 + 3] + bb[tx4 + 3];
            ((float4*)out)[row * 16 + tx] = o;
        }
    }
}

// ---------------------------------------------------------------------------
extern "C" void kernel_launch(void* const* d_in, const int* in_sizes, int n_in,
                              void* d_out, int out_size) {
    const float* X    = (const float*)d_in[0];
    const float* X0   = (const float*)d_in[1];
    const int*   vertex = (const int*)d_in[2];
    const int*   edges  = (const int*)d_in[3];
    const float* W1_w = (const float*)d_in[4];
    const float* W1_b = (const float*)d_in[5];
    const float* W2_w = (const float*)d_in[6];
    const float* W2_b = (const float*)d_in[7];
    const float* W_w  = (const float*)d_in[8];
    const float* W_b  = (const float*)d_in[9];

    float* out   = (float*)d_out;                       // [N_NODES, 64]
    float* XeOut = (float*)d_out + (size_t)N_NODES * D; // [N_EDGES, 64]

    void* sPtr = nullptr;
    void* dPtr = nullptr;
    cudaGetSymbolAddress(&sPtr, g_S);
    cudaGetSymbolAddress(&dPtr, g_deg);

    cudaMemsetAsync(XeOut, 0, (size_t)N_EDGES * D * sizeof(float), 0);
    cudaMemsetAsync(sPtr, 0, (size_t)N_NODES * D * sizeof(float), 0);
    cudaMemsetAsync(dPtr, 0, (size_t)N_NODES * sizeof(int), 0);

    k_pre<<<65, 256>>>(W1_w, W2_w, W2_b, W_w);

    int gemm_blocks = (N_NODES + 63) / 64;              // 1563
    k_gemm_y1<<<gemm_blocks, 256>>>(X, W1_b);

    int sc_blocks = (NNZ * 8) / 256;                    // 31250
    k_scatter_e<<<sc_blocks, 256>>>(vertex, edges, XeOut);
    k_scatter_v<<<sc_blocks, 256>>>(vertex, edges, XeOut);

    k_node_out<<<gemm_blocks, 256>>>(X, X0, W_b, out);
}